// round 12
// baseline (speedup 1.0000x reference)
#include <cuda_runtime.h>
#include <cuda_bf16.h>
#include <cstdint>

// ============================================================================
// LRML scoring, single fused kernel, bf16 m16n8k16 tensor-core GEMM.
// R12 = R10 GEMM tiling (CHUNK=32, NSUB=2, 142 regs — empirical sweet spot)
//     + R11 epilogue improvements (float4 Gram loads, no softmax max-shift)
//     + in-kernel UM/u2/G precompute (no separate launch).
//   logits[n,c] = item[n] . W[c]; columns:
//     c in [0,336): b*21+j -> u_b[d]*K[d,j] (j<20); j==20 -> u_b[d]
//     c in [336,356): mem_m[d] (IM);  [356,360) dead pad
//   score^2 = |u|^2 + |item|^2 - 2 u.item + 2 att.(UM - IM) + att^T G att
// W stored in B-fragment order: block(f,p)=256B, lane owns 8B.
// A row-major bf16 (256B rows), chunk-XOR swizzle phys = c ^ (r&7).
// ============================================================================

#define D_DIM   128
#define M_DIM   20
#define B_USERS 16
#define C_USE   356
#define C_W     360
#define NFRAGS  45
#define CHUNK   32
#define NSUB    2
#define NJ      6
#define LSTRIDE 374
#define GRID    148

// dynamic smem byte offsets
#define WF_BYTES   (48 * 8 * 256)            // 98304
#define AS_OFF     WF_BYTES
#define AS_BYTES   (CHUNK * 256)             // 8192
#define LS_OFF     (AS_OFF + AS_BYTES)
#define LS_BYTES   (16 * LSTRIDE * 4)        // 23936
#define SMEM_TOTAL (LS_OFF + LS_BYTES)       // 130432

__device__ __forceinline__ uint32_t smem_u32(const void* p) {
    uint32_t a;
    asm("{ .reg .u64 t; cvta.to.shared.u64 t, %1; cvt.u32.u64 %0, t; }"
        : "=r"(a) : "l"(p));
    return a;
}
// pack two fp32 into bf16x2 (lo = first element)
__device__ __forceinline__ unsigned bf16pack(float lo, float hi) {
    unsigned r;
    asm("cvt.rn.bf16x2.f32 %0, %1, %2;" : "=r"(r) : "f"(hi), "f"(lo));
    return r;
}

__device__ __forceinline__ void mma_bf16(float* c, const unsigned* a,
                                         unsigned b0, unsigned b1) {
    asm volatile(
        "mma.sync.aligned.m16n8k16.row.col.f32.bf16.bf16.f32 "
        "{%0,%1,%2,%3}, {%4,%5,%6,%7}, {%8,%9}, {%0,%1,%2,%3};"
        : "+f"(c[0]), "+f"(c[1]), "+f"(c[2]), "+f"(c[3])
        : "r"(a[0]), "r"(a[1]), "r"(a[2]), "r"(a[3]), "r"(b0), "r"(b1));
}

__device__ __forceinline__ void ldmatrix4(unsigned* r, uint32_t addr) {
    asm volatile("ldmatrix.sync.aligned.m8n8.x4.shared.b16 {%0,%1,%2,%3}, [%4];"
                 : "=r"(r[0]), "=r"(r[1]), "=r"(r[2]), "=r"(r[3]) : "r"(addr));
}
__device__ __forceinline__ void lds64(unsigned& b0, unsigned& b1, uint32_t addr) {
    asm volatile("ld.shared.v2.u32 {%0,%1}, [%2];" : "=r"(b0), "=r"(b1) : "r"(addr));
}
__device__ __forceinline__ void sts128(uint32_t addr, unsigned w0, unsigned w1,
                                       unsigned w2, unsigned w3) {
    asm volatile("st.shared.v4.u32 [%0], {%1,%2,%3,%4};"
                 :: "r"(addr), "r"(w0), "r"(w1), "r"(w2), "r"(w3) : "memory");
}
__device__ __forceinline__ void sts32(uint32_t addr, unsigned w) {
    asm volatile("st.shared.u32 [%0], %1;" :: "r"(addr), "r"(w) : "memory");
}

__device__ __forceinline__ float2 ffma2(float2 a, float2 b, float2 c) {
    unsigned long long ra = *reinterpret_cast<unsigned long long*>(&a);
    unsigned long long rb = *reinterpret_cast<unsigned long long*>(&b);
    unsigned long long rc = *reinterpret_cast<unsigned long long*>(&c);
    unsigned long long rd;
    asm("fma.rn.f32x2 %0, %1, %2, %3;" : "=l"(rd) : "l"(ra), "l"(rb), "l"(rc));
    return *reinterpret_cast<float2*>(&rd);
}

// ids may be int64 or (silently downcast) int32 — sniff layout.
__device__ __forceinline__ void sniff_uids(const void* ids_raw, int* s_uid) {
    const long long* p64 = (const long long*)ids_raw;
    const int*       p32 = (const int*)ids_raw;
    bool is64 = true;
    for (int i = 0; i < 8; i++) {
        long long v = p64[i];
        if (v < 0 || v >= (1LL << 31)) is64 = false;
    }
    for (int i = 0; i < B_USERS; i++)
        s_uid[i] = is64 ? (int)p64[i] : p32[i];
}

// ----------------------------------------------------------------------------
// Single fused kernel: 148 persistent CTAs, 8 warps, 32-item chunks.
// ----------------------------------------------------------------------------
__global__ void __launch_bounds__(256, 1)
fused_kernel(const float* __restrict__ items,
             const float* __restrict__ users,
             const float* __restrict__ keyM,
             const float* __restrict__ mems,
             const void*  __restrict__ ids_raw,
             float* __restrict__ out, int N)
{
    extern __shared__ char smem_c[];
    float* Ls = (float*)(smem_c + LS_OFF);
    const uint32_t sbase = smem_u32(smem_c);
    const uint32_t Wb = sbase;
    const uint32_t Ab = sbase + AS_OFF;

    __shared__ int s_uid[B_USERS];
    __shared__ float Gs[M_DIM * M_DIM];
    __shared__ float UMs[B_USERS * M_DIM];
    __shared__ float u2s[B_USERS];
    __shared__ float it2s[CHUNK];

    const int tid  = threadIdx.x;
    const int warp = tid >> 5;
    const int lane = tid & 31;
    const int g    = lane >> 2;
    const int tig  = lane & 3;
    const int l15  = lane & 15, hi = lane >> 4, l7 = lane & 7;

    if (tid == 0) sniff_uids(ids_raw, s_uid);
    __syncthreads();

    // ---- build W (bf16) directly in B-fragment order ----
    for (int idx = tid; idx < C_W * 64; idx += 256) {
        int c = idx >> 6, kp = idx & 63;
        float w0 = 0.f, w1 = 0.f;
        int k0 = 2 * kp;
        if (c < B_USERS * 21) {
            int b = c / 21, j = c - b * 21;
            float ua = users[(size_t)s_uid[b] * D_DIM + k0];
            float ub = users[(size_t)s_uid[b] * D_DIM + k0 + 1];
            if (j < M_DIM) {
                w0 = ua * keyM[k0 * M_DIM + j];
                w1 = ub * keyM[(k0 + 1) * M_DIM + j];
            } else { w0 = ua; w1 = ub; }
        } else if (c < C_USE) {
            w0 = mems[(c - B_USERS * 21) * D_DIM + k0];
            w1 = mems[(c - B_USERS * 21) * D_DIM + k0 + 1];
        }
        int f = c >> 3, gg = c & 7;
        int p = kp >> 3, tg = kp & 3, half = (kp >> 2) & 1;
        uint32_t addr = Wb + (uint32_t)((f * 8 + p) * 256 + (4 * gg + tg) * 8 + half * 4);
        sts32(addr, bf16pack(w0, w1));
    }

    // ---- in-kernel precompute: UM (320), u2 (16), G (400) dots, warp-per-dot ----
    for (int t = warp; t < 736; t += 8) {
        const float4 *pa, *pb;
        float* dst;
        if (t < 320) {
            int b = t / M_DIM, m = t - b * M_DIM;
            pa = (const float4*)(users + (size_t)s_uid[b] * D_DIM);
            pb = (const float4*)(mems + m * D_DIM);
            dst = &UMs[t];
        } else if (t < 336) {
            int b = t - 320;
            pa = (const float4*)(users + (size_t)s_uid[b] * D_DIM);
            pb = pa;
            dst = &u2s[b];
        } else {
            int x = t - 336;
            pa = (const float4*)(mems + (x / M_DIM) * D_DIM);
            pb = (const float4*)(mems + (x % M_DIM) * D_DIM);
            dst = &Gs[x];
        }
        float4 a = pa[lane], b = pb[lane];
        float s = a.x * b.x + a.y * b.y + a.z * b.z + a.w * b.w;
#pragma unroll
        for (int o = 16; o; o >>= 1) s += __shfl_xor_sync(0xffffffffu, s, o);
        if (lane == 0) *dst = s;
    }

    // per-thread B-frag base addresses
    uint32_t bjb[NJ];
#pragma unroll
    for (int j = 0; j < NJ; j++) {
        int f = warp + 8 * j;
        if (f >= NFRAGS) f = 0;              // harmless duplicate, never dumped
        bjb[j] = Wb + (uint32_t)(f * 2048 + lane * 8);
    }
    // ldmatrix per-lane bases (A)
    const uint32_t a_base0 = Ab + (uint32_t)(l15 * 256);
    const uint32_t a_base1 = a_base0 + 16 * 256;

    // staging identity: row r = tid>>3 (0..31), q = tid&7; chunks {q, q+8}
    const int st_r = tid >> 3;
    const int st_q = tid & 7;
    const uint32_t st_a1 = Ab + (uint32_t)(st_r * 256 + ((st_q) ^ (st_r & 7)) * 16);
    const uint32_t st_a2 = Ab + (uint32_t)(st_r * 256 + ((st_q + 8) ^ (st_r & 7)) * 16);
    const float4* itemsv = (const float4*)items;

    // ---- prefetch chunk 0 ----
    float4 v0, v1, v2, v3;
    {
        int n = blockIdx.x * CHUNK + st_r;
        if (n < N) {
            const float4* src = itemsv + (size_t)n * 32;
            v0 = src[2 * st_q]; v1 = src[2 * st_q + 1];
            v2 = src[16 + 2 * st_q]; v3 = src[17 + 2 * st_q];
        } else {
            v0 = v1 = v2 = v3 = make_float4(0.f, 0.f, 0.f, 0.f);
        }
    }
    __syncthreads();   // W + precompute visible

    for (int base = blockIdx.x * CHUNK; base < N; base += GRID * CHUNK) {
        // ---- store staged regs -> As (bf16, swizzled), it2 ----
        {
            float s = v0.x*v0.x + v0.y*v0.y + v0.z*v0.z + v0.w*v0.w
                    + v1.x*v1.x + v1.y*v1.y + v1.z*v1.z + v1.w*v1.w
                    + v2.x*v2.x + v2.y*v2.y + v2.z*v2.z + v2.w*v2.w
                    + v3.x*v3.x + v3.y*v3.y + v3.z*v3.z + v3.w*v3.w;
#pragma unroll
            for (int o = 4; o; o >>= 1)
                s += __shfl_down_sync(0xffffffffu, s, o, 8);
            if (st_q == 0) it2s[st_r] = s;

            sts128(st_a1, bf16pack(v0.x, v0.y), bf16pack(v0.z, v0.w),
                          bf16pack(v1.x, v1.y), bf16pack(v1.z, v1.w));
            sts128(st_a2, bf16pack(v2.x, v2.y), bf16pack(v2.z, v2.w),
                          bf16pack(v3.x, v3.y), bf16pack(v3.z, v3.w));
        }
        __syncthreads();

        // ---- prefetch next chunk (hides behind MMA) ----
        {
            int nb = base + GRID * CHUNK;
            if (nb < N) {
                int n = nb + st_r;
                if (n < N) {
                    const float4* src = itemsv + (size_t)n * 32;
                    v0 = src[2 * st_q]; v1 = src[2 * st_q + 1];
                    v2 = src[16 + 2 * st_q]; v3 = src[17 + 2 * st_q];
                } else {
                    v0 = v1 = v2 = v3 = make_float4(0.f, 0.f, 0.f, 0.f);
                }
            }
        }

        // ---- mma mainloop: 8 k16-steps x 2 subtiles x 6 frags ----
        float acc[NSUB][NJ][4];
#pragma unroll
        for (int s = 0; s < NSUB; s++)
#pragma unroll
            for (int j = 0; j < NJ; j++)
#pragma unroll
                for (int q = 0; q < 4; q++) acc[s][j][q] = 0.f;

#pragma unroll
        for (int p = 0; p < 8; p++) {
            const uint32_t phys = (uint32_t)(((2 * p + hi) ^ l7) << 4);
            unsigned a0[4], a1[4];
            ldmatrix4(a0, a_base0 + phys);
            ldmatrix4(a1, a_base1 + phys);
#pragma unroll
            for (int j = 0; j < NJ; j++) {
                unsigned b0, b1;
                lds64(b0, b1, bjb[j] + (uint32_t)(p * 256));
                mma_bf16(acc[0][j], a0, b0, b1);
                mma_bf16(acc[1][j], a1, b0, b1);
            }
        }

        // ---- per-subtile: dump acc -> Ls, then epilogue ----
#pragma unroll 1
        for (int s = 0; s < NSUB; s++) {
            if (s) __syncthreads();
#pragma unroll
            for (int j = 0; j < NJ; j++) {
                int f = warp + 8 * j;
                if (f < NFRAGS) {
                    int col = f * 8 + 2 * tig;
                    *(float2*)&Ls[g * LSTRIDE + col] =
                        make_float2(acc[s][j][0], acc[s][j][1]);
                    *(float2*)&Ls[(g + 8) * LSTRIDE + col] =
                        make_float2(acc[s][j][2], acc[s][j][3]);
                }
            }
            __syncthreads();

            const int b  = tid >> 4;
            const int nl = tid & 15;
            const int n  = base + s * 16 + nl;
            if (n < N) {
                const float* srow = &Ls[nl * LSTRIDE];
                const float* lb = srow + b * 21;

                float l[M_DIM];
#pragma unroll
                for (int j = 0; j < M_DIM; j++) l[j] = lb[j];
                const float uit = lb[M_DIM];

                // softmax numerators without max-shift (|logits| << 1)
                float2 e2[M_DIM / 2];
                float S = 0.f;
#pragma unroll
                for (int j = 0; j < M_DIM / 2; j++) {
                    float ea = __expf(l[2 * j]);
                    float eb = __expf(l[2 * j + 1]);
                    e2[j] = make_float2(ea, eb);
                    S += ea + eb;
                }

                // num1 = e . (UM - IM)
                float2 acc1 = make_float2(0.f, 0.f);
#pragma unroll
                for (int j = 0; j < M_DIM / 2; j++) {
                    float2 um = *(const float2*)&UMs[b * M_DIM + 2 * j];
                    float2 im = *(const float2*)&srow[B_USERS * 21 + 2 * j];
                    acc1 = ffma2(e2[j], make_float2(um.x - im.x, um.y - im.y), acc1);
                }
                float num1 = acc1.x + acc1.y;

                // Q = e^T G e, float4 row loads (rows 16B-aligned: stride 80B)
                float Q = 0.f;
#pragma unroll
                for (int m = 0; m < M_DIM; m++) {
                    const float4* Gr = (const float4*)&Gs[m * M_DIM];
                    float2 ga = make_float2(0.f, 0.f);
#pragma unroll
                    for (int j4 = 0; j4 < 5; j4++) {
                        float4 Gv = Gr[j4];
                        ga = ffma2(make_float2(Gv.x, Gv.y), e2[2 * j4], ga);
                        ga = ffma2(make_float2(Gv.z, Gv.w), e2[2 * j4 + 1], ga);
                    }
                    float em = (m & 1) ? e2[m >> 1].y : e2[m >> 1].x;
                    Q = fmaf(em, ga.x + ga.y, Q);
                }

                float invS = 1.f / S;
                float s2 = u2s[b] + it2s[s * 16 + nl] - 2.f * uit
                         + 2.f * num1 * invS + Q * invS * invS;
                out[(size_t)b * N + n] = -sqrtf(fmaxf(s2, 0.f));
            }
        }
        __syncthreads();   // Ls/it2s/As consumed before next store phase
    }
}

// ----------------------------------------------------------------------------
extern "C" void kernel_launch(void* const* d_in, const int* in_sizes, int n_in,
                              void* d_out, int out_size)
{
    const float* users = (const float*)d_in[0];
    const float* items = (const float*)d_in[1];
    const float* keyM  = (const float*)d_in[2];
    const float* mems  = (const float*)d_in[3];
    const void*  ids   = d_in[4];
    float* out = (float*)d_out;

    const int N = in_sizes[1] / D_DIM;

    cudaFuncSetAttribute(fused_kernel,
                         cudaFuncAttributeMaxDynamicSharedMemorySize, SMEM_TOTAL);

    fused_kernel<<<GRID, 256, SMEM_TOTAL>>>(items, users, keyM, mems, ids, out, N);
}

// round 13
// speedup vs baseline: 1.1636x; 1.1636x over previous
#include <cuda_runtime.h>
#include <cuda_bf16.h>
#include <cstdint>

// ============================================================================
// LRML scoring, fused, bf16 m16n8k16 tensor-core GEMM.
// R13 = R10 exactly (separate pre2 kernel, CHUNK=32/NSUB=2, reg prefetch)
//     + float4 Gram loads and no softmax max-shift in the epilogue.
//   logits[n,c] = item[n] . W[c]; columns:
//     c in [0,336): b*21+j -> u_b[d]*K[d,j] (j<20); j==20 -> u_b[d]
//     c in [336,356): mem_m[d] (IM);  [356,360) dead pad
//   score^2 = |u|^2 + |item|^2 - 2 u.item + 2 att.(UM - IM) + att^T G att
// W stored in B-fragment order: block(f,p)=256B, lane owns 8B.
// A row-major bf16 (256B rows), chunk-XOR swizzle phys = c ^ (r&7).
// ============================================================================

#define D_DIM   128
#define M_DIM   20
#define B_USERS 16
#define C_USE   356
#define C_W     360
#define NFRAGS  45
#define CHUNK   32
#define NSUB    2
#define NJ      6
#define LSTRIDE 374
#define GRID    148

// dynamic smem byte offsets
#define WF_BYTES   (48 * 8 * 256)            // 98304
#define AS_OFF     WF_BYTES
#define AS_BYTES   (CHUNK * 256)             // 8192
#define LS_OFF     (AS_OFF + AS_BYTES)
#define LS_BYTES   (16 * LSTRIDE * 4)        // 23936
#define SMEM_TOTAL (LS_OFF + LS_BYTES)       // 130432

__device__ float g_UM[B_USERS * M_DIM];
__device__ float g_u2[B_USERS];
__device__ float g_G[M_DIM * M_DIM];

__device__ __forceinline__ uint32_t smem_u32(const void* p) {
    uint32_t a;
    asm("{ .reg .u64 t; cvta.to.shared.u64 t, %1; cvt.u32.u64 %0, t; }"
        : "=r"(a) : "l"(p));
    return a;
}
// pack two fp32 into bf16x2 (lo = first element)
__device__ __forceinline__ unsigned bf16pack(float lo, float hi) {
    unsigned r;
    asm("cvt.rn.bf16x2.f32 %0, %1, %2;" : "=r"(r) : "f"(hi), "f"(lo));
    return r;
}

__device__ __forceinline__ void mma_bf16(float* c, const unsigned* a,
                                         unsigned b0, unsigned b1) {
    asm volatile(
        "mma.sync.aligned.m16n8k16.row.col.f32.bf16.bf16.f32 "
        "{%0,%1,%2,%3}, {%4,%5,%6,%7}, {%8,%9}, {%0,%1,%2,%3};"
        : "+f"(c[0]), "+f"(c[1]), "+f"(c[2]), "+f"(c[3])
        : "r"(a[0]), "r"(a[1]), "r"(a[2]), "r"(a[3]), "r"(b0), "r"(b1));
}

__device__ __forceinline__ void ldmatrix4(unsigned* r, uint32_t addr) {
    asm volatile("ldmatrix.sync.aligned.m8n8.x4.shared.b16 {%0,%1,%2,%3}, [%4];"
                 : "=r"(r[0]), "=r"(r[1]), "=r"(r[2]), "=r"(r[3]) : "r"(addr));
}
__device__ __forceinline__ void lds64(unsigned& b0, unsigned& b1, uint32_t addr) {
    asm volatile("ld.shared.v2.u32 {%0,%1}, [%2];" : "=r"(b0), "=r"(b1) : "r"(addr));
}
__device__ __forceinline__ void sts128(uint32_t addr, unsigned w0, unsigned w1,
                                       unsigned w2, unsigned w3) {
    asm volatile("st.shared.v4.u32 [%0], {%1,%2,%3,%4};"
                 :: "r"(addr), "r"(w0), "r"(w1), "r"(w2), "r"(w3) : "memory");
}
__device__ __forceinline__ void sts32(uint32_t addr, unsigned w) {
    asm volatile("st.shared.u32 [%0], %1;" :: "r"(addr), "r"(w) : "memory");
}

__device__ __forceinline__ float2 ffma2(float2 a, float2 b, float2 c) {
    unsigned long long ra = *reinterpret_cast<unsigned long long*>(&a);
    unsigned long long rb = *reinterpret_cast<unsigned long long*>(&b);
    unsigned long long rc = *reinterpret_cast<unsigned long long*>(&c);
    unsigned long long rd;
    asm("fma.rn.f32x2 %0, %1, %2, %3;" : "=l"(rd) : "l"(ra), "l"(rb), "l"(rc));
    return *reinterpret_cast<float2*>(&rd);
}

// ids may be int64 or (silently downcast) int32 — sniff layout.
__device__ __forceinline__ void sniff_uids(const void* ids_raw, int* s_uid) {
    const long long* p64 = (const long long*)ids_raw;
    const int*       p32 = (const int*)ids_raw;
    bool is64 = true;
    for (int i = 0; i < 8; i++) {
        long long v = p64[i];
        if (v < 0 || v >= (1LL << 31)) is64 = false;
    }
    for (int i = 0; i < B_USERS; i++)
        s_uid[i] = is64 ? (int)p64[i] : p32[i];
}

// ----------------------------------------------------------------------------
// pre2: UM, u2, G via one warp per 128-d dot product (736 dots). One launch.
// ----------------------------------------------------------------------------
__global__ void pre2_kernel(const float* __restrict__ users,
                            const float* __restrict__ mems,
                            const void*  __restrict__ ids_raw)
{
    __shared__ int s_uid[B_USERS];
    if (threadIdx.x == 0) sniff_uids(ids_raw, s_uid);
    __syncthreads();

    const int w = blockIdx.x * (blockDim.x >> 5) + (threadIdx.x >> 5);
    const int lane = threadIdx.x & 31;
    const int TOTAL = B_USERS * M_DIM + B_USERS + M_DIM * M_DIM;  // 736
    if (w >= TOTAL) return;

    const float4* pa;
    const float4* pb;
    float* dst;
    if (w < B_USERS * M_DIM) {
        int b = w / M_DIM, m = w % M_DIM;
        pa = (const float4*)(users + (size_t)s_uid[b] * D_DIM);
        pb = (const float4*)(mems + m * D_DIM);
        dst = &g_UM[w];
    } else if (w < B_USERS * M_DIM + B_USERS) {
        int b = w - B_USERS * M_DIM;
        pa = (const float4*)(users + (size_t)s_uid[b] * D_DIM);
        pb = pa;
        dst = &g_u2[b];
    } else {
        int t = w - B_USERS * M_DIM - B_USERS;
        pa = (const float4*)(mems + (t / M_DIM) * D_DIM);
        pb = (const float4*)(mems + (t % M_DIM) * D_DIM);
        dst = &g_G[t];
    }
    float4 a = pa[lane], b = pb[lane];
    float s = a.x * b.x + a.y * b.y + a.z * b.z + a.w * b.w;
#pragma unroll
    for (int o = 16; o; o >>= 1) s += __shfl_xor_sync(0xffffffffu, s, o);
    if (lane == 0) *dst = s;
}

// ----------------------------------------------------------------------------
// Fused bf16 GEMM + epilogue: 148 persistent CTAs, 8 warps, 32-item chunks.
// ----------------------------------------------------------------------------
__global__ void __launch_bounds__(256, 1)
fused_kernel(const float* __restrict__ items,
             const float* __restrict__ users,
             const float* __restrict__ keyM,
             const float* __restrict__ mems,
             const void*  __restrict__ ids_raw,
             float* __restrict__ out, int N)
{
    extern __shared__ char smem_c[];
    float* Ls = (float*)(smem_c + LS_OFF);
    const uint32_t sbase = smem_u32(smem_c);
    const uint32_t Wb = sbase;
    const uint32_t Ab = sbase + AS_OFF;

    __shared__ int s_uid[B_USERS];
    __shared__ __align__(16) float Gs[M_DIM * M_DIM];
    __shared__ float UMs[B_USERS * M_DIM];
    __shared__ float u2s[B_USERS];
    __shared__ float it2s[CHUNK];

    const int tid  = threadIdx.x;
    const int warp = tid >> 5;
    const int lane = tid & 31;
    const int g    = lane >> 2;
    const int tig  = lane & 3;
    const int l15  = lane & 15, hi = lane >> 4, l7 = lane & 7;

    if (tid == 0) sniff_uids(ids_raw, s_uid);
    for (int i = tid; i < M_DIM * M_DIM; i += 256) Gs[i] = g_G[i];
    for (int i = tid; i < B_USERS * M_DIM; i += 256) UMs[i] = g_UM[i];
    if (tid < B_USERS) u2s[tid] = g_u2[tid];
    __syncthreads();

    // ---- build W (bf16) directly in B-fragment order ----
    for (int idx = tid; idx < C_W * 64; idx += 256) {
        int c = idx >> 6, kp = idx & 63;
        float w0 = 0.f, w1 = 0.f;
        int k0 = 2 * kp;
        if (c < B_USERS * 21) {
            int b = c / 21, j = c - b * 21;
            float ua = users[(size_t)s_uid[b] * D_DIM + k0];
            float ub = users[(size_t)s_uid[b] * D_DIM + k0 + 1];
            if (j < M_DIM) {
                w0 = ua * keyM[k0 * M_DIM + j];
                w1 = ub * keyM[(k0 + 1) * M_DIM + j];
            } else { w0 = ua; w1 = ub; }
        } else if (c < C_USE) {
            w0 = mems[(c - B_USERS * 21) * D_DIM + k0];
            w1 = mems[(c - B_USERS * 21) * D_DIM + k0 + 1];
        }
        int f = c >> 3, gg = c & 7;
        int p = kp >> 3, tg = kp & 3, half = (kp >> 2) & 1;
        uint32_t addr = Wb + (uint32_t)((f * 8 + p) * 256 + (4 * gg + tg) * 8 + half * 4);
        sts32(addr, bf16pack(w0, w1));
    }

    // per-thread frag base addresses (B)
    uint32_t bjb[NJ];
#pragma unroll
    for (int j = 0; j < NJ; j++) {
        int f = warp + 8 * j;
        if (f >= NFRAGS) f = 0;              // harmless duplicate, never dumped
        bjb[j] = Wb + (uint32_t)(f * 2048 + lane * 8);
    }
    // ldmatrix per-lane bases (A)
    const uint32_t a_base0 = Ab + (uint32_t)(l15 * 256);
    const uint32_t a_base1 = a_base0 + 16 * 256;

    // staging identity: row r = tid>>3 (0..31), q = tid&7; chunks {q, q+8}
    const int st_r = tid >> 3;
    const int st_q = tid & 7;
    const uint32_t st_a1 = Ab + (uint32_t)(st_r * 256 + ((st_q) ^ (st_r & 7)) * 16);
    const uint32_t st_a2 = Ab + (uint32_t)(st_r * 256 + ((st_q + 8) ^ (st_r & 7)) * 16);
    const float4* itemsv = (const float4*)items;

    // ---- prefetch chunk 0 ----
    float4 v0, v1, v2, v3;
    {
        int n = blockIdx.x * CHUNK + st_r;
        if (n < N) {
            const float4* src = itemsv + (size_t)n * 32;
            v0 = src[2 * st_q]; v1 = src[2 * st_q + 1];
            v2 = src[16 + 2 * st_q]; v3 = src[17 + 2 * st_q];
        } else {
            v0 = v1 = v2 = v3 = make_float4(0.f, 0.f, 0.f, 0.f);
        }
    }
    __syncthreads();   // W build complete

    for (int base = blockIdx.x * CHUNK; base < N; base += GRID * CHUNK) {
        // ---- store staged regs -> As (bf16, swizzled), it2 ----
        {
            float s = v0.x*v0.x + v0.y*v0.y + v0.z*v0.z + v0.w*v0.w
                    + v1.x*v1.x + v1.y*v1.y + v1.z*v1.z + v1.w*v1.w
                    + v2.x*v2.x + v2.y*v2.y + v2.z*v2.z + v2.w*v2.w
                    + v3.x*v3.x + v3.y*v3.y + v3.z*v3.z + v3.w*v3.w;
#pragma unroll
            for (int o = 4; o; o >>= 1)
                s += __shfl_down_sync(0xffffffffu, s, o, 8);
            if (st_q == 0) it2s[st_r] = s;

            sts128(st_a1, bf16pack(v0.x, v0.y), bf16pack(v0.z, v0.w),
                          bf16pack(v1.x, v1.y), bf16pack(v1.z, v1.w));
            sts128(st_a2, bf16pack(v2.x, v2.y), bf16pack(v2.z, v2.w),
                          bf16pack(v3.x, v3.y), bf16pack(v3.z, v3.w));
        }
        __syncthreads();

        // ---- prefetch next chunk (hides behind MMA) ----
        {
            int nb = base + GRID * CHUNK;
            if (nb < N) {
                int n = nb + st_r;
                if (n < N) {
                    const float4* src = itemsv + (size_t)n * 32;
                    v0 = src[2 * st_q]; v1 = src[2 * st_q + 1];
                    v2 = src[16 + 2 * st_q]; v3 = src[17 + 2 * st_q];
                } else {
                    v0 = v1 = v2 = v3 = make_float4(0.f, 0.f, 0.f, 0.f);
                }
            }
        }

        // ---- mma mainloop: 8 k16-steps x 2 subtiles x 6 frags ----
        float acc[NSUB][NJ][4];
#pragma unroll
        for (int s = 0; s < NSUB; s++)
#pragma unroll
            for (int j = 0; j < NJ; j++)
#pragma unroll
                for (int q = 0; q < 4; q++) acc[s][j][q] = 0.f;

#pragma unroll
        for (int p = 0; p < 8; p++) {
            const uint32_t phys = (uint32_t)(((2 * p + hi) ^ l7) << 4);
            unsigned a0[4], a1[4];
            ldmatrix4(a0, a_base0 + phys);
            ldmatrix4(a1, a_base1 + phys);
#pragma unroll
            for (int j = 0; j < NJ; j++) {
                unsigned b0, b1;
                lds64(b0, b1, bjb[j] + (uint32_t)(p * 256));
                mma_bf16(acc[0][j], a0, b0, b1);
                mma_bf16(acc[1][j], a1, b0, b1);
            }
        }

        // ---- per-subtile: dump acc -> Ls, then epilogue ----
#pragma unroll 1
        for (int s = 0; s < NSUB; s++) {
            if (s) __syncthreads();
#pragma unroll
            for (int j = 0; j < NJ; j++) {
                int f = warp + 8 * j;
                if (f < NFRAGS) {
                    int col = f * 8 + 2 * tig;
                    *(float2*)&Ls[g * LSTRIDE + col] =
                        make_float2(acc[s][j][0], acc[s][j][1]);
                    *(float2*)&Ls[(g + 8) * LSTRIDE + col] =
                        make_float2(acc[s][j][2], acc[s][j][3]);
                }
            }
            __syncthreads();

            const int b  = tid >> 4;
            const int nl = tid & 15;
            const int n  = base + s * 16 + nl;
            if (n < N) {
                const float* srow = &Ls[nl * LSTRIDE];
                const float* lb = srow + b * 21;

                float l[M_DIM];
#pragma unroll
                for (int j = 0; j < M_DIM; j++) l[j] = lb[j];
                const float uit = lb[M_DIM];

                // softmax numerators without max-shift (|logits| << 1)
                float2 e2[M_DIM / 2];
                float S = 0.f;
#pragma unroll
                for (int j = 0; j < M_DIM / 2; j++) {
                    float ea = __expf(l[2 * j]);
                    float eb = __expf(l[2 * j + 1]);
                    e2[j] = make_float2(ea, eb);
                    S += ea + eb;
                }

                // num1 = e . (UM - IM)
                float2 acc1 = make_float2(0.f, 0.f);
#pragma unroll
                for (int j = 0; j < M_DIM / 2; j++) {
                    float2 um = *(const float2*)&UMs[b * M_DIM + 2 * j];
                    float2 im = *(const float2*)&srow[B_USERS * 21 + 2 * j];
                    acc1 = ffma2(e2[j], make_float2(um.x - im.x, um.y - im.y), acc1);
                }
                float num1 = acc1.x + acc1.y;

                // Q = e^T G e, float4 row loads (rows 80B apart, 16B-aligned)
                float Q = 0.f;
#pragma unroll
                for (int m = 0; m < M_DIM; m++) {
                    const float4* Gr = (const float4*)&Gs[m * M_DIM];
                    float2 ga = make_float2(0.f, 0.f);
#pragma unroll
                    for (int j4 = 0; j4 < 5; j4++) {
                        float4 Gv = Gr[j4];
                        ga = ffma2(make_float2(Gv.x, Gv.y), e2[2 * j4], ga);
                        ga = ffma2(make_float2(Gv.z, Gv.w), e2[2 * j4 + 1], ga);
                    }
                    float em = (m & 1) ? e2[m >> 1].y : e2[m >> 1].x;
                    Q = fmaf(em, ga.x + ga.y, Q);
                }

                float invS = 1.f / S;
                float s2 = u2s[b] + it2s[s * 16 + nl] - 2.f * uit
                         + 2.f * num1 * invS + Q * invS * invS;
                out[(size_t)b * N + n] = -sqrtf(fmaxf(s2, 0.f));
            }
        }
        __syncthreads();   // Ls/it2s/As consumed before next store phase
    }
}

// ----------------------------------------------------------------------------
extern "C" void kernel_launch(void* const* d_in, const int* in_sizes, int n_in,
                              void* d_out, int out_size)
{
    const float* users = (const float*)d_in[0];
    const float* items = (const float*)d_in[1];
    const float* keyM  = (const float*)d_in[2];
    const float* mems  = (const float*)d_in[3];
    const void*  ids   = d_in[4];
    float* out = (float*)d_out;

    const int N = in_sizes[1] / D_DIM;

    cudaFuncSetAttribute(fused_kernel,
                         cudaFuncAttributeMaxDynamicSharedMemorySize, SMEM_TOTAL);

    pre2_kernel<<<92, 256>>>(users, mems, ids);
    fused_kernel<<<GRID, 256, SMEM_TOTAL>>>(items, users, keyM, mems, ids, out, N);
}

// round 15
// speedup vs baseline: 1.4482x; 1.2446x over previous
#include <cuda_runtime.h>
#include <cuda_bf16.h>
#include <cstdint>

// ============================================================================
// LRML scoring, warp-specialized producer/consumer, bf16 m16n8k16 MMA.
// R15 = R14 with the done[buf] wait moved BEFORE staging (fixes it2s/As
//       overwrite race against slow consumers).
//   warps 0-3 = GEMM producers (stage A, 45 frags = 12/warp, dump->Ls),
//   warps 4-7 = epilogue consumers (256 pairs/chunk, 2/thread, shared G/IM).
//   Double-buffered As/Ls/it2s, named-barrier pipeline:
//     ready[buf] (id 1+buf): producers arrive, consumers sync
//     done[buf]  (id 3+buf): consumers arrive, producers sync (from i>=2)
//     stage[id 5]: producer-internal (128) between staging and mainloop
//   logits[n,c] = item[n] . W[c]; columns:
//     c in [0,336): b*21+j -> u_b[d]*K[d,j] (j<20); j==20 -> u_b[d]
//     c in [336,356): mem_m[d] (IM);  [356,360) dead pad
//   score^2 = |u|^2 + |item|^2 - 2 u.item + 2 att.(UM - IM) + att^T G att
// W stored in B-fragment order: block(f,p)=256B, lane owns 8B.
// A row-major bf16 (256B rows), chunk-XOR swizzle phys = c ^ (r&7).
// ============================================================================

#define D_DIM   128
#define M_DIM   20
#define B_USERS 16
#define C_USE   356
#define C_W     360
#define NFRAGS  45
#define CHUNK   16
#define NJP     12            // frags per producer warp
#define LSTRIDE 374
#define GRID    148

// dynamic smem byte offsets
#define WF_BYTES   (48 * 8 * 256)                 // 98304
#define AS_OFF0    WF_BYTES                       // 98304
#define AS_OFF1    (AS_OFF0 + CHUNK * 256)        // 102400
#define LS_OFF0    (AS_OFF1 + CHUNK * 256)        // 106496
#define LS_BYTES   (CHUNK * LSTRIDE * 4)          // 23936
#define LS_OFF1    (LS_OFF0 + LS_BYTES)           // 130432
#define SMEM_TOTAL (LS_OFF1 + LS_BYTES)           // 154368

#define BAR_SYNC(id, cnt) \
    asm volatile("bar.sync %0, %1;" :: "r"(id), "r"(cnt) : "memory")
#define BAR_ARRIVE(id, cnt) \
    asm volatile("bar.arrive %0, %1;" :: "r"(id), "r"(cnt) : "memory")

__device__ float g_UM[B_USERS * M_DIM];
__device__ float g_u2[B_USERS];
__device__ float g_G[M_DIM * M_DIM];

__device__ __forceinline__ uint32_t smem_u32(const void* p) {
    uint32_t a;
    asm("{ .reg .u64 t; cvta.to.shared.u64 t, %1; cvt.u32.u64 %0, t; }"
        : "=r"(a) : "l"(p));
    return a;
}
__device__ __forceinline__ unsigned bf16pack(float lo, float hi) {
    unsigned r;
    asm("cvt.rn.bf16x2.f32 %0, %1, %2;" : "=r"(r) : "f"(hi), "f"(lo));
    return r;
}
__device__ __forceinline__ void mma_bf16(float* c, const unsigned* a,
                                         unsigned b0, unsigned b1) {
    asm volatile(
        "mma.sync.aligned.m16n8k16.row.col.f32.bf16.bf16.f32 "
        "{%0,%1,%2,%3}, {%4,%5,%6,%7}, {%8,%9}, {%0,%1,%2,%3};"
        : "+f"(c[0]), "+f"(c[1]), "+f"(c[2]), "+f"(c[3])
        : "r"(a[0]), "r"(a[1]), "r"(a[2]), "r"(a[3]), "r"(b0), "r"(b1));
}
__device__ __forceinline__ void ldmatrix4(unsigned* r, uint32_t addr) {
    asm volatile("ldmatrix.sync.aligned.m8n8.x4.shared.b16 {%0,%1,%2,%3}, [%4];"
                 : "=r"(r[0]), "=r"(r[1]), "=r"(r[2]), "=r"(r[3]) : "r"(addr));
}
__device__ __forceinline__ void lds64(unsigned& b0, unsigned& b1, uint32_t addr) {
    asm volatile("ld.shared.v2.u32 {%0,%1}, [%2];" : "=r"(b0), "=r"(b1) : "r"(addr));
}
__device__ __forceinline__ void sts128(uint32_t addr, unsigned w0, unsigned w1,
                                       unsigned w2, unsigned w3) {
    asm volatile("st.shared.v4.u32 [%0], {%1,%2,%3,%4};"
                 :: "r"(addr), "r"(w0), "r"(w1), "r"(w2), "r"(w3) : "memory");
}
__device__ __forceinline__ void sts32(uint32_t addr, unsigned w) {
    asm volatile("st.shared.u32 [%0], %1;" :: "r"(addr), "r"(w) : "memory");
}
__device__ __forceinline__ float2 ffma2(float2 a, float2 b, float2 c) {
    unsigned long long ra = *reinterpret_cast<unsigned long long*>(&a);
    unsigned long long rb = *reinterpret_cast<unsigned long long*>(&b);
    unsigned long long rc = *reinterpret_cast<unsigned long long*>(&c);
    unsigned long long rd;
    asm("fma.rn.f32x2 %0, %1, %2, %3;" : "=l"(rd) : "l"(ra), "l"(rb), "l"(rc));
    return *reinterpret_cast<float2*>(&rd);
}

// ids may be int64 or (silently downcast) int32 — sniff layout.
__device__ __forceinline__ void sniff_uids(const void* ids_raw, int* s_uid) {
    const long long* p64 = (const long long*)ids_raw;
    const int*       p32 = (const int*)ids_raw;
    bool is64 = true;
    for (int i = 0; i < 8; i++) {
        long long v = p64[i];
        if (v < 0 || v >= (1LL << 31)) is64 = false;
    }
    for (int i = 0; i < B_USERS; i++)
        s_uid[i] = is64 ? (int)p64[i] : p32[i];
}

// ----------------------------------------------------------------------------
// pre2: UM, u2, G via one warp per 128-d dot product (736 dots). One launch.
// ----------------------------------------------------------------------------
__global__ void pre2_kernel(const float* __restrict__ users,
                            const float* __restrict__ mems,
                            const void*  __restrict__ ids_raw)
{
    __shared__ int s_uid[B_USERS];
    if (threadIdx.x == 0) sniff_uids(ids_raw, s_uid);
    __syncthreads();

    const int w = blockIdx.x * (blockDim.x >> 5) + (threadIdx.x >> 5);
    const int lane = threadIdx.x & 31;
    const int TOTAL = B_USERS * M_DIM + B_USERS + M_DIM * M_DIM;  // 736
    if (w >= TOTAL) return;

    const float4* pa;
    const float4* pb;
    float* dst;
    if (w < B_USERS * M_DIM) {
        int b = w / M_DIM, m = w % M_DIM;
        pa = (const float4*)(users + (size_t)s_uid[b] * D_DIM);
        pb = (const float4*)(mems + m * D_DIM);
        dst = &g_UM[w];
    } else if (w < B_USERS * M_DIM + B_USERS) {
        int b = w - B_USERS * M_DIM;
        pa = (const float4*)(users + (size_t)s_uid[b] * D_DIM);
        pb = pa;
        dst = &g_u2[b];
    } else {
        int t = w - B_USERS * M_DIM - B_USERS;
        pa = (const float4*)(mems + (t / M_DIM) * D_DIM);
        pb = (const float4*)(mems + (t % M_DIM) * D_DIM);
        dst = &g_G[t];
    }
    float4 a = pa[lane], b = pb[lane];
    float s = a.x * b.x + a.y * b.y + a.z * b.z + a.w * b.w;
#pragma unroll
    for (int o = 16; o; o >>= 1) s += __shfl_xor_sync(0xffffffffu, s, o);
    if (lane == 0) *dst = s;
}

// ----------------------------------------------------------------------------
// Warp-specialized fused kernel: 148 persistent CTAs, 8 warps.
// ----------------------------------------------------------------------------
__global__ void __launch_bounds__(256, 1)
fused_kernel(const float* __restrict__ items,
             const float* __restrict__ users,
             const float* __restrict__ keyM,
             const float* __restrict__ mems,
             const void*  __restrict__ ids_raw,
             float* __restrict__ out, int N)
{
    extern __shared__ char smem_c[];
    const uint32_t sbase = smem_u32(smem_c);
    const uint32_t Wb = sbase;
    const uint32_t AbA[2] = { sbase + AS_OFF0, sbase + AS_OFF1 };
    float* LsA[2] = { (float*)(smem_c + LS_OFF0), (float*)(smem_c + LS_OFF1) };

    __shared__ int s_uid[B_USERS];
    __shared__ __align__(16) float Gs[M_DIM * M_DIM];
    __shared__ float UMs[B_USERS * M_DIM];
    __shared__ float u2s[B_USERS];
    __shared__ float it2s[2][CHUNK];

    const int tid  = threadIdx.x;
    const int warp = tid >> 5;
    const int lane = tid & 31;
    const int g    = lane >> 2;
    const int tig  = lane & 3;
    const int l15  = lane & 15, hi = lane >> 4, l7 = lane & 7;

    if (tid == 0) sniff_uids(ids_raw, s_uid);
    for (int i = tid; i < M_DIM * M_DIM; i += 256) Gs[i] = g_G[i];
    for (int i = tid; i < B_USERS * M_DIM; i += 256) UMs[i] = g_UM[i];
    if (tid < B_USERS) u2s[tid] = g_u2[tid];
    __syncthreads();

    // ---- build W (bf16) directly in B-fragment order (all 256 threads) ----
    for (int idx = tid; idx < C_W * 64; idx += 256) {
        int c = idx >> 6, kp = idx & 63;
        float w0 = 0.f, w1 = 0.f;
        int k0 = 2 * kp;
        if (c < B_USERS * 21) {
            int b = c / 21, j = c - b * 21;
            float ua = users[(size_t)s_uid[b] * D_DIM + k0];
            float ub = users[(size_t)s_uid[b] * D_DIM + k0 + 1];
            if (j < M_DIM) {
                w0 = ua * keyM[k0 * M_DIM + j];
                w1 = ub * keyM[(k0 + 1) * M_DIM + j];
            } else { w0 = ua; w1 = ub; }
        } else if (c < C_USE) {
            w0 = mems[(c - B_USERS * 21) * D_DIM + k0];
            w1 = mems[(c - B_USERS * 21) * D_DIM + k0 + 1];
        }
        int f = c >> 3, gg = c & 7;
        int p = kp >> 3, tg = kp & 3, half = (kp >> 2) & 1;
        uint32_t addr = Wb + (uint32_t)((f * 8 + p) * 256 + (4 * gg + tg) * 8 + half * 4);
        sts32(addr, bf16pack(w0, w1));
    }
    __syncthreads();   // last full-CTA barrier before role split

    const float4* itemsv = (const float4*)items;

    if (tid < 128) {
        // ==================== PRODUCERS (warps 0-3) ====================
        uint32_t bjb[NJP];
        bool fv[NJP];
#pragma unroll
        for (int j = 0; j < NJP; j++) {
            int f = warp + 4 * j;
            fv[j] = (f < NFRAGS);
            if (f >= NFRAGS) f = 0;
            bjb[j] = Wb + (uint32_t)(f * 2048 + lane * 8);
        }
        const int st_r = tid >> 3;       // 0..15
        const int st_q = tid & 7;

        int i = 0;
        for (int base = blockIdx.x * CHUNK; base < N; base += GRID * CHUNK, i++) {
            const int buf = i & 1;
            const uint32_t Ab = AbA[buf];

            // ---- wait consumers done with buf (its Ls/it2s/As) BEFORE
            //      overwriting anything in that buffer ----
            if (i >= 2) BAR_SYNC(3 + buf, 256);

            // ---- stage A (1 slot per thread) + it2 ----
            {
                int n = base + st_r;
                float4 v0, v1, v2, v3;
                if (n < N) {
                    const float4* src = itemsv + (size_t)n * 32;
                    v0 = src[2 * st_q]; v1 = src[2 * st_q + 1];
                    v2 = src[16 + 2 * st_q]; v3 = src[17 + 2 * st_q];
                } else {
                    v0 = v1 = v2 = v3 = make_float4(0.f, 0.f, 0.f, 0.f);
                }
                float s = v0.x*v0.x + v0.y*v0.y + v0.z*v0.z + v0.w*v0.w
                        + v1.x*v1.x + v1.y*v1.y + v1.z*v1.z + v1.w*v1.w
                        + v2.x*v2.x + v2.y*v2.y + v2.z*v2.z + v2.w*v2.w
                        + v3.x*v3.x + v3.y*v3.y + v3.z*v3.z + v3.w*v3.w;
#pragma unroll
                for (int o = 4; o; o >>= 1)
                    s += __shfl_down_sync(0xffffffffu, s, o, 8);
                if (st_q == 0) it2s[buf][st_r] = s;

                uint32_t a1 = Ab + (uint32_t)(st_r * 256 + ((st_q)     ^ (st_r & 7)) * 16);
                uint32_t a2 = Ab + (uint32_t)(st_r * 256 + ((st_q + 8) ^ (st_r & 7)) * 16);
                sts128(a1, bf16pack(v0.x, v0.y), bf16pack(v0.z, v0.w),
                           bf16pack(v1.x, v1.y), bf16pack(v1.z, v1.w));
                sts128(a2, bf16pack(v2.x, v2.y), bf16pack(v2.z, v2.w),
                           bf16pack(v3.x, v3.y), bf16pack(v3.z, v3.w));
            }
            BAR_SYNC(5, 128);   // staging visible to all producer warps

            // ---- mainloop: 8 k16-steps x 12 frags ----
            float acc[NJP][4];
#pragma unroll
            for (int j = 0; j < NJP; j++)
#pragma unroll
                for (int q = 0; q < 4; q++) acc[j][q] = 0.f;

            const uint32_t a_base = Ab + (uint32_t)(l15 * 256);
#pragma unroll
            for (int p = 0; p < 8; p++) {
                const uint32_t phys = (uint32_t)(((2 * p + hi) ^ l7) << 4);
                unsigned a0[4];
                ldmatrix4(a0, a_base + phys);
#pragma unroll
                for (int j = 0; j < NJP; j++) {
                    if (fv[j]) {
                        unsigned b0, b1;
                        lds64(b0, b1, bjb[j] + (uint32_t)(p * 256));
                        mma_bf16(acc[j], a0, b0, b1);
                    }
                }
            }

            // ---- dump acc -> Ls[buf] (safe: done[buf] already held) ----
            float* Ls = LsA[buf];
#pragma unroll
            for (int j = 0; j < NJP; j++) {
                if (fv[j]) {
                    int col = (warp + 4 * j) * 8 + 2 * tig;
                    *(float2*)&Ls[g * LSTRIDE + col] =
                        make_float2(acc[j][0], acc[j][1]);
                    *(float2*)&Ls[(g + 8) * LSTRIDE + col] =
                        make_float2(acc[j][2], acc[j][3]);
                }
            }
            BAR_ARRIVE(1 + buf, 256);   // ready
        }
    } else {
        // ==================== CONSUMERS (warps 4-7) ====================
        const int t2 = tid - 128;
        const int nl = t2 & 15;
        const int b0 = t2 >> 4;          // 0..7; handles b0 and b0+8

        int i = 0;
        for (int base = blockIdx.x * CHUNK; base < N; base += GRID * CHUNK, i++) {
            const int buf = i & 1;
            BAR_SYNC(1 + buf, 256);      // wait ready

            const int n = base + nl;
            if (n < N) {
                const float* srow = &LsA[buf][nl * LSTRIDE];
                const float it2v = it2s[buf][nl];

                // shared IM loads (same nl for both pairs)
                float2 im[M_DIM / 2];
#pragma unroll
                for (int j = 0; j < M_DIM / 2; j++)
                    im[j] = *(const float2*)&srow[B_USERS * 21 + 2 * j];

                float2 e2a[M_DIM / 2], e2b[M_DIM / 2];
                float Sa = 0.f, Sb = 0.f, uita, uitb, n1a = 0.f, n1b = 0.f;
                {
                    const float* lb = srow + b0 * 21;
                    uita = lb[M_DIM];
                    float2 a1 = make_float2(0.f, 0.f);
#pragma unroll
                    for (int j = 0; j < M_DIM / 2; j++) {
                        float ea = __expf(lb[2 * j]);
                        float eb = __expf(lb[2 * j + 1]);
                        e2a[j] = make_float2(ea, eb);
                        Sa += ea + eb;
                        float2 um = *(const float2*)&UMs[b0 * M_DIM + 2 * j];
                        a1 = ffma2(e2a[j], make_float2(um.x - im[j].x, um.y - im[j].y), a1);
                    }
                    n1a = a1.x + a1.y;
                }
                {
                    const float* lb = srow + (b0 + 8) * 21;
                    uitb = lb[M_DIM];
                    float2 a1 = make_float2(0.f, 0.f);
#pragma unroll
                    for (int j = 0; j < M_DIM / 2; j++) {
                        float ea = __expf(lb[2 * j]);
                        float eb = __expf(lb[2 * j + 1]);
                        e2b[j] = make_float2(ea, eb);
                        Sb += ea + eb;
                        float2 um = *(const float2*)&UMs[(b0 + 8) * M_DIM + 2 * j];
                        a1 = ffma2(e2b[j], make_float2(um.x - im[j].x, um.y - im[j].y), a1);
                    }
                    n1b = a1.x + a1.y;
                }

                // fused Gram: G rows loaded once, used for both pairs
                float Qa = 0.f, Qb = 0.f;
#pragma unroll
                for (int m = 0; m < M_DIM; m++) {
                    const float4* Gr = (const float4*)&Gs[m * M_DIM];
                    float2 ga = make_float2(0.f, 0.f);
                    float2 gb = make_float2(0.f, 0.f);
#pragma unroll
                    for (int j4 = 0; j4 < 5; j4++) {
                        float4 Gv = Gr[j4];
                        float2 glo = make_float2(Gv.x, Gv.y);
                        float2 ghi = make_float2(Gv.z, Gv.w);
                        ga = ffma2(glo, e2a[2 * j4], ga);
                        ga = ffma2(ghi, e2a[2 * j4 + 1], ga);
                        gb = ffma2(glo, e2b[2 * j4], gb);
                        gb = ffma2(ghi, e2b[2 * j4 + 1], gb);
                    }
                    float ema = (m & 1) ? e2a[m >> 1].y : e2a[m >> 1].x;
                    float emb = (m & 1) ? e2b[m >> 1].y : e2b[m >> 1].x;
                    Qa = fmaf(ema, ga.x + ga.y, Qa);
                    Qb = fmaf(emb, gb.x + gb.y, Qb);
                }

                float iSa = 1.f / Sa, iSb = 1.f / Sb;
                float s2a = u2s[b0] + it2v - 2.f * uita
                          + 2.f * n1a * iSa + Qa * iSa * iSa;
                float s2b = u2s[b0 + 8] + it2v - 2.f * uitb
                          + 2.f * n1b * iSb + Qb * iSb * iSb;
                out[(size_t)b0 * N + n]       = -sqrtf(fmaxf(s2a, 0.f));
                out[(size_t)(b0 + 8) * N + n] = -sqrtf(fmaxf(s2b, 0.f));
            }

            BAR_ARRIVE(3 + buf, 256);    // done
        }
    }
}

// ----------------------------------------------------------------------------
extern "C" void kernel_launch(void* const* d_in, const int* in_sizes, int n_in,
                              void* d_out, int out_size)
{
    const float* users = (const float*)d_in[0];
    const float* items = (const float*)d_in[1];
    const float* keyM  = (const float*)d_in[2];
    const float* mems  = (const float*)d_in[3];
    const void*  ids   = d_in[4];
    float* out = (float*)d_out;

    const int N = in_sizes[1] / D_DIM;

    cudaFuncSetAttribute(fused_kernel,
                         cudaFuncAttributeMaxDynamicSharedMemorySize, SMEM_TOTAL);

    pre2_kernel<<<92, 256>>>(users, mems, ids);
    fused_kernel<<<GRID, 256, SMEM_TOTAL>>>(items, users, keyM, mems, ids, out, N);
}

// round 17
// speedup vs baseline: 1.5844x; 1.0940x over previous
#include <cuda_runtime.h>
#include <cuda_bf16.h>
#include <cstdint>

// ============================================================================
// LRML scoring, warp-specialized producer/consumer, bf16 m16n8k16 MMA.
// R17 = R16 resubmitted verbatim (A/B against "container failed twice":
//       R14 failed the same way and the near-identical R15 passed, so the
//       error mode is suspected infra, not kernel. If this fails again,
//       that's conclusive and R18 reverts to the R15 structure.)
//   512 threads: 8 producer + 8 consumer warps, CHUNK=32.
//   Producers: stage A (1 slot/thread), 45 frags = 6/warp x 2 subtiles,
//              dump->Ls.  Consumers: 512 pairs/chunk, 2/thread (b0, b0+8)
//              with shared G/IM loads.
//   Double-buffered As/Ls/it2s, named-barrier pipeline:
//     ready[buf] (id 1+buf, 512): producers arrive, consumers sync
//     done[buf]  (id 3+buf, 512): consumers arrive, producers sync (i>=2)
//     stage[id 5, 256]: producer-internal between staging and mainloop
//   logits[n,c] = item[n] . W[c]; columns:
//     c in [0,336): b*21+j -> u_b[d]*K[d,j] (j<20); j==20 -> u_b[d]
//     c in [336,356): mem_m[d] (IM);  [356,360) dead pad
//   score^2 = |u|^2 + |item|^2 - 2 u.item + 2 att.(UM - IM) + att^T G att
// W stored in B-fragment order: block(f,p)=256B, lane owns 8B.
// A row-major bf16 (256B rows), chunk-XOR swizzle phys = c ^ (r&7).
// ============================================================================

#define D_DIM   128
#define M_DIM   20
#define B_USERS 16
#define C_USE   356
#define C_W     360
#define NFRAGS  45
#define CHUNK   32
#define NSUB    2
#define NJP     6             // frags per producer warp
#define THREADS 512
#define LSTRIDE 374
#define GRID    148

// dynamic smem byte offsets
#define WF_BYTES   (48 * 8 * 256)                 // 98304
#define AS_OFF0    WF_BYTES                       // 98304
#define AS_OFF1    (AS_OFF0 + CHUNK * 256)        // 106496
#define LS_OFF0    (AS_OFF1 + CHUNK * 256)        // 114688
#define LS_BYTES   (CHUNK * LSTRIDE * 4)          // 47872
#define LS_OFF1    (LS_OFF0 + LS_BYTES)           // 162560
#define SMEM_TOTAL (LS_OFF1 + LS_BYTES)           // 210432

#define BAR_SYNC(id, cnt) \
    asm volatile("bar.sync %0, %1;" :: "r"(id), "r"(cnt) : "memory")
#define BAR_ARRIVE(id, cnt) \
    asm volatile("bar.arrive %0, %1;" :: "r"(id), "r"(cnt) : "memory")

__device__ float g_UM[B_USERS * M_DIM];
__device__ float g_u2[B_USERS];
__device__ float g_G[M_DIM * M_DIM];

__device__ __forceinline__ uint32_t smem_u32(const void* p) {
    uint32_t a;
    asm("{ .reg .u64 t; cvta.to.shared.u64 t, %1; cvt.u32.u64 %0, t; }"
        : "=r"(a) : "l"(p));
    return a;
}
__device__ __forceinline__ unsigned bf16pack(float lo, float hi) {
    unsigned r;
    asm("cvt.rn.bf16x2.f32 %0, %1, %2;" : "=r"(r) : "f"(hi), "f"(lo));
    return r;
}
__device__ __forceinline__ void mma_bf16(float* c, const unsigned* a,
                                         unsigned b0, unsigned b1) {
    asm volatile(
        "mma.sync.aligned.m16n8k16.row.col.f32.bf16.bf16.f32 "
        "{%0,%1,%2,%3}, {%4,%5,%6,%7}, {%8,%9}, {%0,%1,%2,%3};"
        : "+f"(c[0]), "+f"(c[1]), "+f"(c[2]), "+f"(c[3])
        : "r"(a[0]), "r"(a[1]), "r"(a[2]), "r"(a[3]), "r"(b0), "r"(b1));
}
__device__ __forceinline__ void ldmatrix4(unsigned* r, uint32_t addr) {
    asm volatile("ldmatrix.sync.aligned.m8n8.x4.shared.b16 {%0,%1,%2,%3}, [%4];"
                 : "=r"(r[0]), "=r"(r[1]), "=r"(r[2]), "=r"(r[3]) : "r"(addr));
}
__device__ __forceinline__ void lds64(unsigned& b0, unsigned& b1, uint32_t addr) {
    asm volatile("ld.shared.v2.u32 {%0,%1}, [%2];" : "=r"(b0), "=r"(b1) : "r"(addr));
}
__device__ __forceinline__ void sts128(uint32_t addr, unsigned w0, unsigned w1,
                                       unsigned w2, unsigned w3) {
    asm volatile("st.shared.v4.u32 [%0], {%1,%2,%3,%4};"
                 :: "r"(addr), "r"(w0), "r"(w1), "r"(w2), "r"(w3) : "memory");
}
__device__ __forceinline__ void sts32(uint32_t addr, unsigned w) {
    asm volatile("st.shared.u32 [%0], %1;" :: "r"(addr), "r"(w) : "memory");
}
__device__ __forceinline__ float2 ffma2(float2 a, float2 b, float2 c) {
    unsigned long long ra = *reinterpret_cast<unsigned long long*>(&a);
    unsigned long long rb = *reinterpret_cast<unsigned long long*>(&b);
    unsigned long long rc = *reinterpret_cast<unsigned long long*>(&c);
    unsigned long long rd;
    asm("fma.rn.f32x2 %0, %1, %2, %3;" : "=l"(rd) : "l"(ra), "l"(rb), "l"(rc));
    return *reinterpret_cast<float2*>(&rd);
}

// ids may be int64 or (silently downcast) int32 — sniff layout.
__device__ __forceinline__ void sniff_uids(const void* ids_raw, int* s_uid) {
    const long long* p64 = (const long long*)ids_raw;
    const int*       p32 = (const int*)ids_raw;
    bool is64 = true;
    for (int i = 0; i < 8; i++) {
        long long v = p64[i];
        if (v < 0 || v >= (1LL << 31)) is64 = false;
    }
    for (int i = 0; i < B_USERS; i++)
        s_uid[i] = is64 ? (int)p64[i] : p32[i];
}

// ----------------------------------------------------------------------------
// pre2: UM, u2, G via one warp per 128-d dot product (736 dots). One launch.
// ----------------------------------------------------------------------------
__global__ void pre2_kernel(const float* __restrict__ users,
                            const float* __restrict__ mems,
                            const void*  __restrict__ ids_raw)
{
    __shared__ int s_uid[B_USERS];
    if (threadIdx.x == 0) sniff_uids(ids_raw, s_uid);
    __syncthreads();

    const int w = blockIdx.x * (blockDim.x >> 5) + (threadIdx.x >> 5);
    const int lane = threadIdx.x & 31;
    const int TOTAL = B_USERS * M_DIM + B_USERS + M_DIM * M_DIM;  // 736
    if (w >= TOTAL) return;

    const float4* pa;
    const float4* pb;
    float* dst;
    if (w < B_USERS * M_DIM) {
        int b = w / M_DIM, m = w % M_DIM;
        pa = (const float4*)(users + (size_t)s_uid[b] * D_DIM);
        pb = (const float4*)(mems + m * D_DIM);
        dst = &g_UM[w];
    } else if (w < B_USERS * M_DIM + B_USERS) {
        int b = w - B_USERS * M_DIM;
        pa = (const float4*)(users + (size_t)s_uid[b] * D_DIM);
        pb = pa;
        dst = &g_u2[b];
    } else {
        int t = w - B_USERS * M_DIM - B_USERS;
        pa = (const float4*)(mems + (t / M_DIM) * D_DIM);
        pb = (const float4*)(mems + (t % M_DIM) * D_DIM);
        dst = &g_G[t];
    }
    float4 a = pa[lane], b = pb[lane];
    float s = a.x * b.x + a.y * b.y + a.z * b.z + a.w * b.w;
#pragma unroll
    for (int o = 16; o; o >>= 1) s += __shfl_xor_sync(0xffffffffu, s, o);
    if (lane == 0) *dst = s;
}

// ----------------------------------------------------------------------------
// Warp-specialized fused kernel: 148 persistent CTAs, 16 warps.
// ----------------------------------------------------------------------------
__global__ void __launch_bounds__(THREADS, 1)
fused_kernel(const float* __restrict__ items,
             const float* __restrict__ users,
             const float* __restrict__ keyM,
             const float* __restrict__ mems,
             const void*  __restrict__ ids_raw,
             float* __restrict__ out, int N)
{
    extern __shared__ char smem_c[];
    const uint32_t sbase = smem_u32(smem_c);
    const uint32_t Wb = sbase;
    const uint32_t AbA[2] = { sbase + AS_OFF0, sbase + AS_OFF1 };
    float* LsA[2] = { (float*)(smem_c + LS_OFF0), (float*)(smem_c + LS_OFF1) };

    __shared__ int s_uid[B_USERS];
    __shared__ __align__(16) float Gs[M_DIM * M_DIM];
    __shared__ float UMs[B_USERS * M_DIM];
    __shared__ float u2s[B_USERS];
    __shared__ float it2s[2][CHUNK];

    const int tid  = threadIdx.x;
    const int warp = tid >> 5;
    const int lane = tid & 31;
    const int g    = lane >> 2;
    const int tig  = lane & 3;
    const int l15  = lane & 15, hi = lane >> 4, l7 = lane & 7;

    if (tid == 0) sniff_uids(ids_raw, s_uid);
    for (int i = tid; i < M_DIM * M_DIM; i += THREADS) Gs[i] = g_G[i];
    for (int i = tid; i < B_USERS * M_DIM; i += THREADS) UMs[i] = g_UM[i];
    if (tid < B_USERS) u2s[tid] = g_u2[tid];
    __syncthreads();

    // ---- build W (bf16) directly in B-fragment order (all threads) ----
    for (int idx = tid; idx < C_W * 64; idx += THREADS) {
        int c = idx >> 6, kp = idx & 63;
        float w0 = 0.f, w1 = 0.f;
        int k0 = 2 * kp;
        if (c < B_USERS * 21) {
            int b = c / 21, j = c - b * 21;
            float ua = users[(size_t)s_uid[b] * D_DIM + k0];
            float ub = users[(size_t)s_uid[b] * D_DIM + k0 + 1];
            if (j < M_DIM) {
                w0 = ua * keyM[k0 * M_DIM + j];
                w1 = ub * keyM[(k0 + 1) * M_DIM + j];
            } else { w0 = ua; w1 = ub; }
        } else if (c < C_USE) {
            w0 = mems[(c - B_USERS * 21) * D_DIM + k0];
            w1 = mems[(c - B_USERS * 21) * D_DIM + k0 + 1];
        }
        int f = c >> 3, gg = c & 7;
        int p = kp >> 3, tg = kp & 3, half = (kp >> 2) & 1;
        uint32_t addr = Wb + (uint32_t)((f * 8 + p) * 256 + (4 * gg + tg) * 8 + half * 4);
        sts32(addr, bf16pack(w0, w1));
    }
    __syncthreads();   // last full-CTA barrier before role split

    const float4* itemsv = (const float4*)items;

    if (tid < 256) {
        // ==================== PRODUCERS (warps 0-7) ====================
        uint32_t bjb[NJP];
        bool fv[NJP];
#pragma unroll
        for (int j = 0; j < NJP; j++) {
            int f = warp + 8 * j;
            fv[j] = (f < NFRAGS);
            if (f >= NFRAGS) f = 0;
            bjb[j] = Wb + (uint32_t)(f * 2048 + lane * 8);
        }
        const int st_r = tid >> 3;       // 0..31
        const int st_q = tid & 7;

        int i = 0;
        for (int base = blockIdx.x * CHUNK; base < N; base += GRID * CHUNK, i++) {
            const int buf = i & 1;
            const uint32_t Ab = AbA[buf];

            // wait consumers done with buf before overwriting it
            if (i >= 2) BAR_SYNC(3 + buf, THREADS);

            // ---- stage A (1 slot per thread) + it2 ----
            {
                int n = base + st_r;
                float4 v0, v1, v2, v3;
                if (n < N) {
                    const float4* src = itemsv + (size_t)n * 32;
                    v0 = src[2 * st_q]; v1 = src[2 * st_q + 1];
                    v2 = src[16 + 2 * st_q]; v3 = src[17 + 2 * st_q];
                } else {
                    v0 = v1 = v2 = v3 = make_float4(0.f, 0.f, 0.f, 0.f);
                }
                float s = v0.x*v0.x + v0.y*v0.y + v0.z*v0.z + v0.w*v0.w
                        + v1.x*v1.x + v1.y*v1.y + v1.z*v1.z + v1.w*v1.w
                        + v2.x*v2.x + v2.y*v2.y + v2.z*v2.z + v2.w*v2.w
                        + v3.x*v3.x + v3.y*v3.y + v3.z*v3.z + v3.w*v3.w;
#pragma unroll
                for (int o = 4; o; o >>= 1)
                    s += __shfl_down_sync(0xffffffffu, s, o, 8);
                if (st_q == 0) it2s[buf][st_r] = s;

                uint32_t a1 = Ab + (uint32_t)(st_r * 256 + ((st_q)     ^ (st_r & 7)) * 16);
                uint32_t a2 = Ab + (uint32_t)(st_r * 256 + ((st_q + 8) ^ (st_r & 7)) * 16);
                sts128(a1, bf16pack(v0.x, v0.y), bf16pack(v0.z, v0.w),
                           bf16pack(v1.x, v1.y), bf16pack(v1.z, v1.w));
                sts128(a2, bf16pack(v2.x, v2.y), bf16pack(v2.z, v2.w),
                           bf16pack(v3.x, v3.y), bf16pack(v3.z, v3.w));
            }
            BAR_SYNC(5, 256);   // staging visible to all producer warps

            // ---- mainloop: 8 k16-steps x 2 subtiles x 6 frags ----
            float acc[NSUB][NJP][4];
#pragma unroll
            for (int s = 0; s < NSUB; s++)
#pragma unroll
                for (int j = 0; j < NJP; j++)
#pragma unroll
                    for (int q = 0; q < 4; q++) acc[s][j][q] = 0.f;

            const uint32_t a_base0 = Ab + (uint32_t)(l15 * 256);
            const uint32_t a_base1 = a_base0 + 16 * 256;
#pragma unroll
            for (int p = 0; p < 8; p++) {
                const uint32_t phys = (uint32_t)(((2 * p + hi) ^ l7) << 4);
                unsigned a0[4], a1[4];
                ldmatrix4(a0, a_base0 + phys);
                ldmatrix4(a1, a_base1 + phys);
#pragma unroll
                for (int j = 0; j < NJP; j++) {
                    if (fv[j]) {
                        unsigned b0, b1;
                        lds64(b0, b1, bjb[j] + (uint32_t)(p * 256));
                        mma_bf16(acc[0][j], a0, b0, b1);
                        mma_bf16(acc[1][j], a1, b0, b1);
                    }
                }
            }

            // ---- dump acc -> Ls[buf] ----
            float* Ls = LsA[buf];
#pragma unroll
            for (int s = 0; s < NSUB; s++) {
#pragma unroll
                for (int j = 0; j < NJP; j++) {
                    if (fv[j]) {
                        int col = (warp + 8 * j) * 8 + 2 * tig;
                        *(float2*)&Ls[(s * 16 + g) * LSTRIDE + col] =
                            make_float2(acc[s][j][0], acc[s][j][1]);
                        *(float2*)&Ls[(s * 16 + g + 8) * LSTRIDE + col] =
                            make_float2(acc[s][j][2], acc[s][j][3]);
                    }
                }
            }
            BAR_ARRIVE(1 + buf, THREADS);   // ready
        }
    } else {
        // ==================== CONSUMERS (warps 8-15) ====================
        const int t2 = tid - 256;
        const int nl = t2 & 31;          // 0..31
        const int b0 = t2 >> 5;          // 0..7; handles b0 and b0+8

        int i = 0;
        for (int base = blockIdx.x * CHUNK; base < N; base += GRID * CHUNK, i++) {
            const int buf = i & 1;
            BAR_SYNC(1 + buf, THREADS);  // wait ready

            const int n = base + nl;
            if (n < N) {
                const float* srow = &LsA[buf][nl * LSTRIDE];
                const float it2v = it2s[buf][nl];

                // shared IM loads (same nl for both pairs)
                float2 im[M_DIM / 2];
#pragma unroll
                for (int j = 0; j < M_DIM / 2; j++)
                    im[j] = *(const float2*)&srow[B_USERS * 21 + 2 * j];

                float2 e2a[M_DIM / 2], e2b[M_DIM / 2];
                float Sa = 0.f, Sb = 0.f, uita, uitb, n1a = 0.f, n1b = 0.f;
                {
                    const float* lb = srow + b0 * 21;
                    uita = lb[M_DIM];
                    float2 a1 = make_float2(0.f, 0.f);
#pragma unroll
                    for (int j = 0; j < M_DIM / 2; j++) {
                        float ea = __expf(lb[2 * j]);
                        float eb = __expf(lb[2 * j + 1]);
                        e2a[j] = make_float2(ea, eb);
                        Sa += ea + eb;
                        float2 um = *(const float2*)&UMs[b0 * M_DIM + 2 * j];
                        a1 = ffma2(e2a[j], make_float2(um.x - im[j].x, um.y - im[j].y), a1);
                    }
                    n1a = a1.x + a1.y;
                }
                {
                    const float* lb = srow + (b0 + 8) * 21;
                    uitb = lb[M_DIM];
                    float2 a1 = make_float2(0.f, 0.f);
#pragma unroll
                    for (int j = 0; j < M_DIM / 2; j++) {
                        float ea = __expf(lb[2 * j]);
                        float eb = __expf(lb[2 * j + 1]);
                        e2b[j] = make_float2(ea, eb);
                        Sb += ea + eb;
                        float2 um = *(const float2*)&UMs[(b0 + 8) * M_DIM + 2 * j];
                        a1 = ffma2(e2b[j], make_float2(um.x - im[j].x, um.y - im[j].y), a1);
                    }
                    n1b = a1.x + a1.y;
                }

                // fused Gram: G rows loaded once, used for both pairs
                float Qa = 0.f, Qb = 0.f;
#pragma unroll
                for (int m = 0; m < M_DIM; m++) {
                    const float4* Gr = (const float4*)&Gs[m * M_DIM];
                    float2 ga = make_float2(0.f, 0.f);
                    float2 gb = make_float2(0.f, 0.f);
#pragma unroll
                    for (int j4 = 0; j4 < 5; j4++) {
                        float4 Gv = Gr[j4];
                        float2 glo = make_float2(Gv.x, Gv.y);
                        float2 ghi = make_float2(Gv.z, Gv.w);
                        ga = ffma2(glo, e2a[2 * j4], ga);
                        ga = ffma2(ghi, e2a[2 * j4 + 1], ga);
                        gb = ffma2(glo, e2b[2 * j4], gb);
                        gb = ffma2(ghi, e2b[2 * j4 + 1], gb);
                    }
                    float ema = (m & 1) ? e2a[m >> 1].y : e2a[m >> 1].x;
                    float emb = (m & 1) ? e2b[m >> 1].y : e2b[m >> 1].x;
                    Qa = fmaf(ema, ga.x + ga.y, Qa);
                    Qb = fmaf(emb, gb.x + gb.y, Qb);
                }

                float iSa = 1.f / Sa, iSb = 1.f / Sb;
                float s2a = u2s[b0] + it2v - 2.f * uita
                          + 2.f * n1a * iSa + Qa * iSa * iSa;
                float s2b = u2s[b0 + 8] + it2v - 2.f * uitb
                          + 2.f * n1b * iSb + Qb * iSb * iSb;
                out[(size_t)b0 * N + n]       = -sqrtf(fmaxf(s2a, 0.f));
                out[(size_t)(b0 + 8) * N + n] = -sqrtf(fmaxf(s2b, 0.f));
            }

            BAR_ARRIVE(3 + buf, THREADS);    // done
        }
    }
}

// ----------------------------------------------------------------------------
extern "C" void kernel_launch(void* const* d_in, const int* in_sizes, int n_in,
                              void* d_out, int out_size)
{
    const float* users = (const float*)d_in[0];
    const float* items = (const float*)d_in[1];
    const float* keyM  = (const float*)d_in[2];
    const float* mems  = (const float*)d_in[3];
    const void*  ids   = d_in[4];
    float* out = (float*)d_out;

    const int N = in_sizes[1] / D_DIM;

    cudaFuncSetAttribute(fused_kernel,
                         cudaFuncAttributeMaxDynamicSharedMemorySize, SMEM_TOTAL);

    pre2_kernel<<<92, 256>>>(users, mems, ids);
    fused_kernel<<<GRID, THREADS, SMEM_TOTAL>>>(items, users, keyM, mems, ids, out, N);
}